// round 4
// baseline (speedup 1.0000x reference)
#include <cuda_runtime.h>
#include <cuda_fp16.h>
#include <math.h>
#include <stdint.h>

// Problem constants
#define T_TOK 512
#define H_DIM 2048
#define E_NUM 64
#define TOPK  8
#define I_DIM 768

// ---------------- scratch ----------------
__device__ float g_act[T_TOK * TOPK * I_DIM];
__device__ float g_partial[(size_t)T_TOK * TOPK * H_DIM];
__device__ float g_sact[T_TOK * I_DIM];
__device__ int   g_counts[E_NUM];
__device__ int   g_offsets[E_NUM + 1];
__device__ int   g_cursor[E_NUM];
__device__ int   g_tki[T_TOK * TOPK];
__device__ float g_tkw[T_TOK * TOPK];
__device__ int   g_tok[T_TOK * TOPK];
__device__ int   g_dest[T_TOK * TOPK];
__device__ float g_slotw[T_TOK * TOPK];

// ---------------- router ----------------
__global__ void router_kernel(const float* __restrict__ x,
                              const float* __restrict__ gate_w,
                              const float* __restrict__ gate_b) {
    int t = blockIdx.x;
    __shared__ float sx[H_DIM];
    __shared__ float sscore[E_NUM];
    __shared__ float sbias[E_NUM];
    int tid = threadIdx.x;  // 0..63

    const float4* xr = (const float4*)(x + (size_t)t * H_DIM);
    float4* sx4 = (float4*)sx;
    for (int i = tid; i < H_DIM / 4; i += 64) sx4[i] = xr[i];
    __syncthreads();

    const float* w = gate_w + (size_t)tid * H_DIM;
    float acc = 0.f;
    #pragma unroll 4
    for (int h = 0; h < H_DIM; h += 4) {
        float4 wv = *(const float4*)(w + h);
        acc += wv.x * sx[h] + wv.y * sx[h + 1] + wv.z * sx[h + 2] + wv.w * sx[h + 3];
    }
    float score = 1.f / (1.f + expf(-acc));
    sscore[tid] = score;
    sbias[tid]  = score + gate_b[tid];
    __syncthreads();

    if (tid == 0) {
        int   idx[TOPK];
        float wts[TOPK];
        float sum = 0.f;
        for (int k = 0; k < TOPK; k++) {
            float best = -1e30f; int bi = 0;
            for (int e = 0; e < E_NUM; e++) {
                float v = sbias[e];
                if (v > best) { best = v; bi = e; }
            }
            sbias[bi] = -1e30f;
            idx[k] = bi;
            wts[k] = sscore[bi];
            sum += wts[k];
        }
        float inv = 1.f / (sum + 1e-20f);
        for (int k = 0; k < TOPK; k++) {
            g_tki[t * TOPK + k] = idx[k];
            g_tkw[t * TOPK + k] = wts[k] * inv;
            atomicAdd(&g_counts[idx[k]], 1);
        }
    }
}

__global__ void zero_counts_kernel() { g_counts[threadIdx.x] = 0; }

__global__ void offsets_kernel() {
    int o = 0;
    for (int e = 0; e < E_NUM; e++) {
        g_offsets[e] = o;
        o += g_counts[e];
        g_cursor[e] = 0;
    }
    g_offsets[E_NUM] = o;
}

__global__ void scatter_kernel() {
    int i = blockIdx.x * blockDim.x + threadIdx.x;
    if (i >= T_TOK * TOPK) return;
    int e = g_tki[i];
    int pos = g_offsets[e] + atomicAdd(&g_cursor[e], 1);
    g_tok[pos]   = i / TOPK;
    g_dest[pos]  = i;
    g_slotw[pos] = g_tkw[i];
}

// ---------------- tensor-core helpers ----------------
__device__ __forceinline__ uint32_t smem_u32(const void* p) {
    return (uint32_t)__cvta_generic_to_shared(p);
}
__device__ __forceinline__ void ldsm4(uint32_t* r, uint32_t addr) {
    asm volatile("ldmatrix.sync.aligned.m8n8.x4.shared.b16 {%0,%1,%2,%3}, [%4];"
                 : "=r"(r[0]), "=r"(r[1]), "=r"(r[2]), "=r"(r[3]) : "r"(addr));
}
__device__ __forceinline__ void ldsm2t(uint32_t* r, uint32_t addr) {
    asm volatile("ldmatrix.sync.aligned.m8n8.x2.trans.shared.b16 {%0,%1}, [%2];"
                 : "=r"(r[0]), "=r"(r[1]) : "r"(addr));
}
__device__ __forceinline__ void mma16816(float* c, const uint32_t* a, const uint32_t* b) {
    asm volatile(
        "mma.sync.aligned.m16n8k16.row.col.f32.f16.f16.f32 "
        "{%0,%1,%2,%3}, {%4,%5,%6,%7}, {%8,%9}, {%0,%1,%2,%3};"
        : "+f"(c[0]), "+f"(c[1]), "+f"(c[2]), "+f"(c[3])
        : "r"(a[0]), "r"(a[1]), "r"(a[2]), "r"(a[3]), "r"(b[0]), "r"(b[1]));
}

// split-fp16: 4 floats -> hi + lo
__device__ __forceinline__ void cvt4_hilo(const float4& va, __half* hrow, __half* lrow) {
    float f[4] = {va.x, va.y, va.z, va.w};
    #pragma unroll
    for (int j = 0; j < 4; j += 2) {
        __half h0 = __float2half(f[j]);
        __half h1 = __float2half(f[j + 1]);
        __half l0 = __float2half(f[j]     - __half2float(h0));
        __half l1 = __float2half(f[j + 1] - __half2float(h1));
        *(__half2*)(hrow + j) = __halves2half2(h0, h1);
        *(__half2*)(lrow + j) = __halves2half2(l0, l1);
    }
}
// plain fp16: 8 floats -> hi only
__device__ __forceinline__ void cvt8_hi(const float4& va, const float4& vb, __half* hrow) {
    float f[8] = {va.x, va.y, va.z, va.w, vb.x, vb.y, vb.z, vb.w};
    #pragma unroll
    for (int j = 0; j < 8; j += 2)
        *(__half2*)(hrow + j) = __halves2half2(__float2half(f[j]), __float2half(f[j + 1]));
}

#define ASTRIDE16 24  // halfs per A row, BK=16 (48B stride: 3r mod 8 distinct -> conflict-free)
#define ASTRIDE32 40  // halfs per A row, BK=32 (80B stride: 5r mod 8 distinct -> conflict-free)
#define BSTRIDE  136  // halfs per B row, BN=128 (272B stride: r mod 8 distinct -> conflict-free)

// ---------------- grouped dual-B GEMM + fused SiLU ----------------
// fp16 split-A x fp16 B (2 MMAs). BM=64, BN=128, BK=16.
// Double-buffered smem + depth-2 register prefetch; one sync per K-iter.
template <bool SHARED>
__global__ void __launch_bounds__(256) gateup_kernel(
    const float* __restrict__ x,
    const float* __restrict__ w_gate_all,
    const float* __restrict__ w_up_all) {

    const int e = SHARED ? 0 : blockIdx.z;
    int base, nrows;
    if (SHARED) { base = 0; nrows = T_TOK; }
    else        { base = g_offsets[e]; nrows = g_offsets[e + 1] - base; }

    const int m0 = blockIdx.y * 64;
    if (m0 >= nrows) return;
    const int n0 = blockIdx.x * 128;

    const float* wg = SHARED ? w_gate_all : (w_gate_all + (size_t)e * H_DIM * I_DIM);
    const float* wu = SHARED ? w_up_all   : (w_up_all   + (size_t)e * H_DIM * I_DIM);

    __shared__ __align__(16) __half Ah[2][64][ASTRIDE16];
    __shared__ __align__(16) __half Al[2][64][ASTRIDE16];
    __shared__ __align__(16) __half Bg[2][16][BSTRIDE];
    __shared__ __align__(16) __half Bu[2][16][BSTRIDE];

    const int tid = threadIdx.x;
    // A loader: row = tid/4 (64), k-offset (tid%4)*4  -> one float4
    const int ar  = tid >> 2;
    const int akb = (tid & 3) * 4;
    const bool avalid = (m0 + ar < nrows);
    int tokid = 0;
    if (avalid) tokid = SHARED ? (m0 + ar) : g_tok[base + m0 + ar];
    const float* aptr = x + (size_t)tokid * H_DIM + akb;
    // B loader: k-row = tid/16 (16), n-offset (tid%16)*8 -> two float4 per matrix
    const int bk = tid >> 4;
    const int bn = (tid & 15) * 8;
    const float* gptr = wg + (size_t)bk * I_DIM + n0 + bn;
    const float* uptr = wu + (size_t)bk * I_DIM + n0 + bn;

    const int wid  = tid >> 5;
    const int lane = tid & 31;
    const int wm = wid >> 2;   // 0..1
    const int wn = wid & 3;    // 0..3
    const int g  = lane >> 2;
    const int tg = lane & 3;

    float cg[2][4][4] = {};
    float cu[2][4][4] = {};

    const float4 z4 = make_float4(0.f, 0.f, 0.f, 0.f);
    // prefetch registers: [set][0]=A, [1..2]=Bg, [3..4]=Bu
    float4 P[2][5];

    const int NIT = H_DIM / 16;

    #pragma unroll
    for (int s = 0; s < 2; s++) {
        int k = s * 16;
        P[s][0] = avalid ? *(const float4*)(aptr + k) : z4;
        const float* gp = gptr + (size_t)k * I_DIM;
        const float* up = uptr + (size_t)k * I_DIM;
        P[s][1] = *(const float4*)(gp);
        P[s][2] = *(const float4*)(gp + 4);
        P[s][3] = *(const float4*)(up);
        P[s][4] = *(const float4*)(up + 4);
    }
    // store stage 0
    cvt4_hilo(P[0][0], &Ah[0][ar][akb], &Al[0][ar][akb]);
    cvt8_hi(P[0][1], P[0][2], &Bg[0][bk][bn]);
    cvt8_hi(P[0][3], P[0][4], &Bu[0][bk][bn]);
    __syncthreads();

    for (int it = 0; it < NIT; it++) {
        const int cur = it & 1;
        const int nxt = cur ^ 1;

        // issue loads for it+2 into P[cur] (its tile already in smem)
        if (it + 2 < NIT) {
            int k = (it + 2) * 16;
            P[cur][0] = avalid ? *(const float4*)(aptr + k) : z4;
            const float* gp = gptr + (size_t)k * I_DIM;
            const float* up = uptr + (size_t)k * I_DIM;
            P[cur][1] = *(const float4*)(gp);
            P[cur][2] = *(const float4*)(gp + 4);
            P[cur][3] = *(const float4*)(up);
            P[cur][4] = *(const float4*)(up + 4);
        }

        // MMAs on stage cur
        {
            uint32_t ah_f[2][4], al_f[2][4];
            #pragma unroll
            for (int mi = 0; mi < 2; mi++) {
                int row = wm * 32 + mi * 16 + (lane & 15);
                int col = (lane & 16) >> 1;
                ldsm4(ah_f[mi], smem_u32(&Ah[cur][row][col]));
                ldsm4(al_f[mi], smem_u32(&Al[cur][row][col]));
            }
            uint32_t bg_f[4][2], bu_f[4][2];
            #pragma unroll
            for (int ni = 0; ni < 4; ni++) {
                int brow = lane & 15;
                int bcol = wn * 32 + ni * 8;
                ldsm2t(bg_f[ni], smem_u32(&Bg[cur][brow][bcol]));
                ldsm2t(bu_f[ni], smem_u32(&Bu[cur][brow][bcol]));
            }
            #pragma unroll
            for (int mi = 0; mi < 2; mi++) {
                #pragma unroll
                for (int ni = 0; ni < 4; ni++) {
                    mma16816(cg[mi][ni], ah_f[mi], bg_f[ni]);
                    mma16816(cg[mi][ni], al_f[mi], bg_f[ni]);
                    mma16816(cu[mi][ni], ah_f[mi], bu_f[ni]);
                    mma16816(cu[mi][ni], al_f[mi], bu_f[ni]);
                }
            }
        }

        // store tile for it+1 (loaded one iter ago) into the other buffer
        if (it + 1 < NIT) {
            cvt4_hilo(P[nxt][0], &Ah[nxt][ar][akb], &Al[nxt][ar][akb]);
            cvt8_hi(P[nxt][1], P[nxt][2], &Bg[nxt][bk][bn]);
            cvt8_hi(P[nxt][3], P[nxt][4], &Bu[nxt][bk][bn]);
        }
        __syncthreads();
    }

    // epilogue: silu(g)*u
    #pragma unroll
    for (int mi = 0; mi < 2; mi++) {
        int r0 = m0 + wm * 32 + mi * 16 + g;
        int r1 = r0 + 8;
        #pragma unroll
        for (int ni = 0; ni < 4; ni++) {
            int c0 = n0 + wn * 32 + ni * 8 + tg * 2;
            if (r0 < nrows) {
                float* orow = SHARED ? (g_sact + (size_t)r0 * I_DIM)
                                     : (g_act  + (size_t)(base + r0) * I_DIM);
                float g0 = cg[mi][ni][0], u0 = cu[mi][ni][0];
                float g1 = cg[mi][ni][1], u1 = cu[mi][ni][1];
                orow[c0]     = (g0 / (1.f + expf(-g0))) * u0;
                orow[c0 + 1] = (g1 / (1.f + expf(-g1))) * u1;
            }
            if (r1 < nrows) {
                float* orow = SHARED ? (g_sact + (size_t)r1 * I_DIM)
                                     : (g_act  + (size_t)(base + r1) * I_DIM);
                float g2 = cg[mi][ni][2], u2 = cu[mi][ni][2];
                float g3 = cg[mi][ni][3], u3 = cu[mi][ni][3];
                orow[c0]     = (g2 / (1.f + expf(-g2))) * u2;
                orow[c0 + 1] = (g3 / (1.f + expf(-g3))) * u3;
            }
        }
    }
}

// ---------------- grouped down-proj GEMM ----------------
// fp16 split-A x fp16 B. BM=64, BN=128, BK=32. Double-buffered + depth-2 prefetch.
template <bool SHARED>
__global__ void __launch_bounds__(256) down_kernel(
    const float* __restrict__ w_down_all,
    float* __restrict__ out) {

    const int e = SHARED ? 0 : blockIdx.z;
    int base, nrows;
    if (SHARED) { base = 0; nrows = T_TOK; }
    else        { base = g_offsets[e]; nrows = g_offsets[e + 1] - base; }

    const int m0 = blockIdx.y * 64;
    if (m0 >= nrows) return;
    const int n0 = blockIdx.x * 128;

    const float* wd = SHARED ? w_down_all : (w_down_all + (size_t)e * I_DIM * H_DIM);
    const float* Asrc = SHARED ? g_sact : g_act;

    __shared__ __align__(16) __half Ah[2][64][ASTRIDE32];
    __shared__ __align__(16) __half Al[2][64][ASTRIDE32];
    __shared__ __align__(16) __half Bh[2][32][BSTRIDE];

    const int tid = threadIdx.x;
    const int ar  = tid >> 2;
    const int akb = (tid & 3) * 8;   // 8 floats (2 float4)
    const bool avalid = (m0 + ar < nrows);
    const float* aptr = Asrc + (size_t)(base + (avalid ? (m0 + ar) : 0)) * I_DIM + akb;

    const int bk = tid >> 3;         // 32 rows
    const int bn = (tid & 7) * 16;   // 16 floats (4 float4)
    const float* bptr = wd + (size_t)bk * H_DIM + n0 + bn;

    const int wid  = tid >> 5;
    const int lane = tid & 31;
    const int wm = wid >> 2;
    const int wn = wid & 3;
    const int g  = lane >> 2;
    const int tg = lane & 3;

    float acc[2][4][4] = {};

    const float4 z4 = make_float4(0.f, 0.f, 0.f, 0.f);
    // prefetch: [set][0..1]=A, [2..5]=B
    float4 P[2][6];
    const int NIT = I_DIM / 32;

    #pragma unroll
    for (int s = 0; s < 2; s++) {
        int k = s * 32;
        P[s][0] = avalid ? *(const float4*)(aptr + k)     : z4;
        P[s][1] = avalid ? *(const float4*)(aptr + k + 4) : z4;
        const float* bp = bptr + (size_t)k * H_DIM;
        #pragma unroll
        for (int j = 0; j < 4; j++) P[s][2 + j] = *(const float4*)(bp + j * 4);
    }
    cvt4_hilo(P[0][0], &Ah[0][ar][akb],     &Al[0][ar][akb]);
    cvt4_hilo(P[0][1], &Ah[0][ar][akb + 4], &Al[0][ar][akb + 4]);
    cvt8_hi(P[0][2], P[0][3], &Bh[0][bk][bn]);
    cvt8_hi(P[0][4], P[0][5], &Bh[0][bk][bn + 8]);
    __syncthreads();

    for (int it = 0; it < NIT; it++) {
        const int cur = it & 1;
        const int nxt = cur ^ 1;

        if (it + 2 < NIT) {
            int k = (it + 2) * 32;
            P[cur][0] = avalid ? *(const float4*)(aptr + k)     : z4;
            P[cur][1] = avalid ? *(const float4*)(aptr + k + 4) : z4;
            const float* bp = bptr + (size_t)k * H_DIM;
            #pragma unroll
            for (int j = 0; j < 4; j++) P[cur][2 + j] = *(const float4*)(bp + j * 4);
        }

        #pragma unroll
        for (int ks = 0; ks < 32; ks += 16) {
            uint32_t ah_f[2][4], al_f[2][4];
            #pragma unroll
            for (int mi = 0; mi < 2; mi++) {
                int row = wm * 32 + mi * 16 + (lane & 15);
                int col = ks + ((lane & 16) >> 1);
                ldsm4(ah_f[mi], smem_u32(&Ah[cur][row][col]));
                ldsm4(al_f[mi], smem_u32(&Al[cur][row][col]));
            }
            uint32_t b_f[4][2];
            #pragma unroll
            for (int ni = 0; ni < 4; ni++) {
                int brow = ks + (lane & 15);
                int bcol = wn * 32 + ni * 8;
                ldsm2t(b_f[ni], smem_u32(&Bh[cur][brow][bcol]));
            }
            #pragma unroll
            for (int mi = 0; mi < 2; mi++) {
                #pragma unroll
                for (int ni = 0; ni < 4; ni++) {
                    mma16816(acc[mi][ni], ah_f[mi], b_f[ni]);
                    mma16816(acc[mi][ni], al_f[mi], b_f[ni]);
                }
            }
        }

        if (it + 1 < NIT) {
            cvt4_hilo(P[nxt][0], &Ah[nxt][ar][akb],     &Al[nxt][ar][akb]);
            cvt4_hilo(P[nxt][1], &Ah[nxt][ar][akb + 4], &Al[nxt][ar][akb + 4]);
            cvt8_hi(P[nxt][2], P[nxt][3], &Bh[nxt][bk][bn]);
            cvt8_hi(P[nxt][4], P[nxt][5], &Bh[nxt][bk][bn + 8]);
        }
        __syncthreads();
    }

    #pragma unroll
    for (int mi = 0; mi < 2; mi++) {
        int rr[2] = {m0 + wm * 32 + mi * 16 + g, m0 + wm * 32 + mi * 16 + g + 8};
        #pragma unroll
        for (int half = 0; half < 2; half++) {
            int r = rr[half];
            if (r >= nrows) continue;
            #pragma unroll
            for (int ni = 0; ni < 4; ni++) {
                int c0 = n0 + wn * 32 + ni * 8 + tg * 2;
                float v0 = acc[mi][ni][half * 2 + 0];
                float v1 = acc[mi][ni][half * 2 + 1];
                if (SHARED) {
                    float* orow = out + (size_t)r * H_DIM;
                    orow[c0]     = v0;
                    orow[c0 + 1] = v1;
                } else {
                    int slot = base + r;
                    int dest = g_dest[slot];
                    float w  = g_slotw[slot];
                    float* orow = g_partial + (size_t)dest * H_DIM;
                    orow[c0]     = w * v0;
                    orow[c0 + 1] = w * v1;
                }
            }
        }
    }
}

// ---------------- combine ----------------
__global__ void combine_kernel(float* __restrict__ out) {
    int i = blockIdx.x * blockDim.x + threadIdx.x;
    int t = i / H_DIM;
    int h = i - t * H_DIM;
    float acc = out[i];
    #pragma unroll
    for (int k = 0; k < TOPK; k++)
        acc += g_partial[((size_t)t * TOPK + k) * H_DIM + h];
    out[i] = acc;
}

// ---------------- launch ----------------
extern "C" void kernel_launch(void* const* d_in, const int* in_sizes, int n_in,
                              void* d_out, int out_size) {
    const float* x       = (const float*)d_in[0];
    const float* gate_w  = (const float*)d_in[1];
    const float* gate_b  = (const float*)d_in[2];
    const float* w_gate  = (const float*)d_in[3];
    const float* w_up    = (const float*)d_in[4];
    const float* w_down  = (const float*)d_in[5];
    const float* sw_gate = (const float*)d_in[6];
    const float* sw_up   = (const float*)d_in[7];
    const float* sw_down = (const float*)d_in[8];
    float* out = (float*)d_out;

    zero_counts_kernel<<<1, 64>>>();
    router_kernel<<<T_TOK, 64>>>(x, gate_w, gate_b);
    offsets_kernel<<<1, 1>>>();
    scatter_kernel<<<(T_TOK * TOPK + 255) / 256, 256>>>();

    gateup_kernel<false><<<dim3(I_DIM / 128, 8, E_NUM), 256>>>(x, w_gate, w_up);
    gateup_kernel<true><<<dim3(I_DIM / 128, T_TOK / 64, 1), 256>>>(x, sw_gate, sw_up);
    down_kernel<false><<<dim3(H_DIM / 128, 8, E_NUM), 256>>>(w_down, nullptr);
    down_kernel<true><<<dim3(H_DIM / 128, T_TOK / 64, 1), 256>>>(sw_down, out);
    combine_kernel<<<(T_TOK * H_DIM) / 256, 256>>>(out);
}

// round 5
// speedup vs baseline: 1.4806x; 1.4806x over previous
#include <cuda_runtime.h>
#include <cuda_fp16.h>
#include <math.h>
#include <stdint.h>

// Problem constants
#define T_TOK 512
#define H_DIM 2048
#define E_NUM 64
#define TOPK  8
#define I_DIM 768

// ---------------- scratch ----------------
__device__ float g_act[T_TOK * TOPK * I_DIM];
__device__ float g_partial[(size_t)T_TOK * TOPK * H_DIM];
__device__ float g_sact[T_TOK * I_DIM];
__device__ int   g_counts[E_NUM];
__device__ int   g_offsets[E_NUM + 1];
__device__ int   g_cursor[E_NUM];
__device__ int   g_tki[T_TOK * TOPK];
__device__ float g_tkw[T_TOK * TOPK];
__device__ int   g_tok[T_TOK * TOPK];
__device__ int   g_dest[T_TOK * TOPK];
__device__ float g_slotw[T_TOK * TOPK];

// ---------------- router ----------------
__global__ void router_kernel(const float* __restrict__ x,
                              const float* __restrict__ gate_w,
                              const float* __restrict__ gate_b) {
    int t = blockIdx.x;
    __shared__ float sx[H_DIM];
    __shared__ float sscore[E_NUM];
    __shared__ float sbias[E_NUM];
    int tid = threadIdx.x;  // 0..63

    const float4* xr = (const float4*)(x + (size_t)t * H_DIM);
    float4* sx4 = (float4*)sx;
    for (int i = tid; i < H_DIM / 4; i += 64) sx4[i] = xr[i];
    __syncthreads();

    const float* w = gate_w + (size_t)tid * H_DIM;
    float acc = 0.f;
    #pragma unroll 4
    for (int h = 0; h < H_DIM; h += 4) {
        float4 wv = *(const float4*)(w + h);
        acc += wv.x * sx[h] + wv.y * sx[h + 1] + wv.z * sx[h + 2] + wv.w * sx[h + 3];
    }
    float score = 1.f / (1.f + expf(-acc));
    sscore[tid] = score;
    sbias[tid]  = score + gate_b[tid];
    __syncthreads();

    if (tid == 0) {
        int   idx[TOPK];
        float wts[TOPK];
        float sum = 0.f;
        for (int k = 0; k < TOPK; k++) {
            float best = -1e30f; int bi = 0;
            for (int e = 0; e < E_NUM; e++) {
                float v = sbias[e];
                if (v > best) { best = v; bi = e; }
            }
            sbias[bi] = -1e30f;
            idx[k] = bi;
            wts[k] = sscore[bi];
            sum += wts[k];
        }
        float inv = 1.f / (sum + 1e-20f);
        for (int k = 0; k < TOPK; k++) {
            g_tki[t * TOPK + k] = idx[k];
            g_tkw[t * TOPK + k] = wts[k] * inv;
            atomicAdd(&g_counts[idx[k]], 1);
        }
    }
}

__global__ void zero_counts_kernel() { g_counts[threadIdx.x] = 0; }

__global__ void offsets_kernel() {
    int o = 0;
    for (int e = 0; e < E_NUM; e++) {
        g_offsets[e] = o;
        o += g_counts[e];
        g_cursor[e] = 0;
    }
    g_offsets[E_NUM] = o;
}

__global__ void scatter_kernel() {
    int i = blockIdx.x * blockDim.x + threadIdx.x;
    if (i >= T_TOK * TOPK) return;
    int e = g_tki[i];
    int pos = g_offsets[e] + atomicAdd(&g_cursor[e], 1);
    g_tok[pos]   = i / TOPK;
    g_dest[pos]  = i;
    g_slotw[pos] = g_tkw[i];
}

// ---------------- tensor-core helpers ----------------
__device__ __forceinline__ uint32_t smem_u32(const void* p) {
    return (uint32_t)__cvta_generic_to_shared(p);
}
__device__ __forceinline__ void ldsm4(uint32_t* r, uint32_t addr) {
    asm volatile("ldmatrix.sync.aligned.m8n8.x4.shared.b16 {%0,%1,%2,%3}, [%4];"
                 : "=r"(r[0]), "=r"(r[1]), "=r"(r[2]), "=r"(r[3]) : "r"(addr));
}
__device__ __forceinline__ void ldsm2t(uint32_t* r, uint32_t addr) {
    asm volatile("ldmatrix.sync.aligned.m8n8.x2.trans.shared.b16 {%0,%1}, [%2];"
                 : "=r"(r[0]), "=r"(r[1]) : "r"(addr));
}
__device__ __forceinline__ void mma16816(float* c, const uint32_t* a, const uint32_t* b) {
    asm volatile(
        "mma.sync.aligned.m16n8k16.row.col.f32.f16.f16.f32 "
        "{%0,%1,%2,%3}, {%4,%5,%6,%7}, {%8,%9}, {%0,%1,%2,%3};"
        : "+f"(c[0]), "+f"(c[1]), "+f"(c[2]), "+f"(c[3])
        : "r"(a[0]), "r"(a[1]), "r"(a[2]), "r"(a[3]), "r"(b[0]), "r"(b[1]));
}

// split-fp16: 8 floats -> hi + lo halves
__device__ __forceinline__ void cvt8_hilo(const float4& va, const float4& vb,
                                          __half* hrow, __half* lrow) {
    float f[8] = {va.x, va.y, va.z, va.w, vb.x, vb.y, vb.z, vb.w};
    #pragma unroll
    for (int j = 0; j < 8; j += 2) {
        __half h0 = __float2half(f[j]);
        __half h1 = __float2half(f[j + 1]);
        __half l0 = __float2half(f[j]     - __half2float(h0));
        __half l1 = __float2half(f[j + 1] - __half2float(h1));
        *(__half2*)(hrow + j) = __halves2half2(h0, h1);
        *(__half2*)(lrow + j) = __halves2half2(l0, l1);
    }
}
// plain fp16: 8 floats -> hi only
__device__ __forceinline__ void cvt8_hi(const float4& va, const float4& vb, __half* hrow) {
    float f[8] = {va.x, va.y, va.z, va.w, vb.x, vb.y, vb.z, vb.w};
    #pragma unroll
    for (int j = 0; j < 8; j += 2)
        *(__half2*)(hrow + j) = __halves2half2(__float2half(f[j]), __float2half(f[j + 1]));
}

#define ASTRIDE 40  // halfs per A smem row (80B: banks 20r mod 32 distinct over 8 rows)
#define BSTRIDE 72  // halfs per B smem row (144B: banks 4r mod 32 distinct over 8 rows)

// ---------------- grouped dual-B GEMM + fused SiLU ----------------
// fp16 split-A x fp16 B (4 MMAs per microtile pair). BM=64, BN=64, BK=32.
// 128 threads = 4 warps (2M x 2N), warp tile 32x32. Small CTA -> 3 CTAs/SM.
template <bool SHARED>
__global__ void __launch_bounds__(128) gateup_kernel(
    const float* __restrict__ x,
    const float* __restrict__ w_gate_all,
    const float* __restrict__ w_up_all) {

    const int e = SHARED ? 0 : blockIdx.z;
    int base, nrows;
    if (SHARED) { base = 0; nrows = T_TOK; }
    else        { base = g_offsets[e]; nrows = g_offsets[e + 1] - base; }

    const int m0 = blockIdx.y * 64;
    if (m0 >= nrows) return;
    const int n0 = blockIdx.x * 64;

    const float* wg = SHARED ? w_gate_all : (w_gate_all + (size_t)e * H_DIM * I_DIM);
    const float* wu = SHARED ? w_up_all   : (w_up_all   + (size_t)e * H_DIM * I_DIM);

    __shared__ __align__(16) __half Ah[64][ASTRIDE];
    __shared__ __align__(16) __half Al[64][ASTRIDE];
    __shared__ __align__(16) __half Bg[32][BSTRIDE];
    __shared__ __align__(16) __half Bu[32][BSTRIDE];

    const int tid = threadIdx.x;
    // A loader: row = tid/2 (64 rows), k-offset (tid%2)*16 -> 16 floats
    const int ar  = tid >> 1;
    const int akb = (tid & 1) * 16;
    const bool avalid = (m0 + ar < nrows);
    int tokid = 0;
    if (avalid) tokid = SHARED ? (m0 + ar) : g_tok[base + m0 + ar];
    const float* aptr = x + (size_t)tokid * H_DIM + akb;
    // B loader: k-row = tid/4 (32 rows), n-offset (tid%4)*16 -> 16 floats per matrix
    const int bk = tid >> 2;
    const int bn = (tid & 3) * 16;
    const float* gptr = wg + (size_t)bk * I_DIM + n0 + bn;
    const float* uptr = wu + (size_t)bk * I_DIM + n0 + bn;

    const int wid  = tid >> 5;
    const int lane = tid & 31;
    const int wm = wid >> 1;   // 0..1
    const int wn = wid & 1;    // 0..1
    const int g  = lane >> 2;
    const int tg = lane & 3;

    float cg[2][4][4] = {};
    float cu[2][4][4] = {};

    const float4 z4 = make_float4(0.f, 0.f, 0.f, 0.f);
    float4 pa[4], pg[4], pu[4];
    #pragma unroll
    for (int j = 0; j < 4; j++) {
        pa[j] = avalid ? *(const float4*)(aptr + j * 4) : z4;
        pg[j] = *(const float4*)(gptr + j * 4);
        pu[j] = *(const float4*)(uptr + j * 4);
    }

    for (int k0 = 0; k0 < H_DIM; k0 += 32) {
        cvt8_hilo(pa[0], pa[1], &Ah[ar][akb],     &Al[ar][akb]);
        cvt8_hilo(pa[2], pa[3], &Ah[ar][akb + 8], &Al[ar][akb + 8]);
        cvt8_hi(pg[0], pg[1], &Bg[bk][bn]);
        cvt8_hi(pg[2], pg[3], &Bg[bk][bn + 8]);
        cvt8_hi(pu[0], pu[1], &Bu[bk][bn]);
        cvt8_hi(pu[2], pu[3], &Bu[bk][bn + 8]);
        __syncthreads();

        if (k0 + 32 < H_DIM) {
            int kn = k0 + 32;
            const float* gp = gptr + (size_t)kn * I_DIM;
            const float* up = uptr + (size_t)kn * I_DIM;
            #pragma unroll
            for (int j = 0; j < 4; j++) {
                pa[j] = avalid ? *(const float4*)(aptr + kn + j * 4) : z4;
                pg[j] = *(const float4*)(gp + j * 4);
                pu[j] = *(const float4*)(up + j * 4);
            }
        }

        #pragma unroll
        for (int ks = 0; ks < 32; ks += 16) {
            uint32_t ah_f[2][4], al_f[2][4];
            #pragma unroll
            for (int mi = 0; mi < 2; mi++) {
                int row = wm * 32 + mi * 16 + (lane & 15);
                int col = ks + ((lane & 16) >> 1);
                ldsm4(ah_f[mi], smem_u32(&Ah[row][col]));
                ldsm4(al_f[mi], smem_u32(&Al[row][col]));
            }
            uint32_t bg_f[4][2], bu_f[4][2];
            #pragma unroll
            for (int ni = 0; ni < 4; ni++) {
                int brow = ks + (lane & 15);
                int bcol = wn * 32 + ni * 8;
                ldsm2t(bg_f[ni], smem_u32(&Bg[brow][bcol]));
                ldsm2t(bu_f[ni], smem_u32(&Bu[brow][bcol]));
            }
            #pragma unroll
            for (int mi = 0; mi < 2; mi++) {
                #pragma unroll
                for (int ni = 0; ni < 4; ni++) {
                    mma16816(cg[mi][ni], ah_f[mi], bg_f[ni]);
                    mma16816(cg[mi][ni], al_f[mi], bg_f[ni]);
                    mma16816(cu[mi][ni], ah_f[mi], bu_f[ni]);
                    mma16816(cu[mi][ni], al_f[mi], bu_f[ni]);
                }
            }
        }
        __syncthreads();
    }

    // epilogue: silu(g)*u
    #pragma unroll
    for (int mi = 0; mi < 2; mi++) {
        int r0 = m0 + wm * 32 + mi * 16 + g;
        int r1 = r0 + 8;
        #pragma unroll
        for (int ni = 0; ni < 4; ni++) {
            int c0 = n0 + wn * 32 + ni * 8 + tg * 2;
            if (r0 < nrows) {
                float* orow = SHARED ? (g_sact + (size_t)r0 * I_DIM)
                                     : (g_act  + (size_t)(base + r0) * I_DIM);
                float g0 = cg[mi][ni][0], u0 = cu[mi][ni][0];
                float g1 = cg[mi][ni][1], u1 = cu[mi][ni][1];
                orow[c0]     = (g0 / (1.f + expf(-g0))) * u0;
                orow[c0 + 1] = (g1 / (1.f + expf(-g1))) * u1;
            }
            if (r1 < nrows) {
                float* orow = SHARED ? (g_sact + (size_t)r1 * I_DIM)
                                     : (g_act  + (size_t)(base + r1) * I_DIM);
                float g2 = cg[mi][ni][2], u2 = cu[mi][ni][2];
                float g3 = cg[mi][ni][3], u3 = cu[mi][ni][3];
                orow[c0]     = (g2 / (1.f + expf(-g2))) * u2;
                orow[c0 + 1] = (g3 / (1.f + expf(-g3))) * u3;
            }
        }
    }
}

// ---------------- grouped down-proj GEMM ----------------
// fp16 split-A x fp16 B. BM=64, BN=64, BK=32, 128 threads (2x2 warps, 32x32 tile).
template <bool SHARED>
__global__ void __launch_bounds__(128) down_kernel(
    const float* __restrict__ w_down_all,
    float* __restrict__ out) {

    const int e = SHARED ? 0 : blockIdx.z;
    int base, nrows;
    if (SHARED) { base = 0; nrows = T_TOK; }
    else        { base = g_offsets[e]; nrows = g_offsets[e + 1] - base; }

    const int m0 = blockIdx.y * 64;
    if (m0 >= nrows) return;
    const int n0 = blockIdx.x * 64;

    const float* wd = SHARED ? w_down_all : (w_down_all + (size_t)e * I_DIM * H_DIM);
    const float* Asrc = SHARED ? g_sact : g_act;

    __shared__ __align__(16) __half Ah[64][ASTRIDE];
    __shared__ __align__(16) __half Al[64][ASTRIDE];
    __shared__ __align__(16) __half Bh[32][BSTRIDE];

    const int tid = threadIdx.x;
    const int ar  = tid >> 1;
    const int akb = (tid & 1) * 16;
    const bool avalid = (m0 + ar < nrows);
    const float* aptr = Asrc + (size_t)(base + (avalid ? (m0 + ar) : 0)) * I_DIM + akb;

    const int bk = tid >> 2;
    const int bn = (tid & 3) * 16;
    const float* bptr = wd + (size_t)bk * H_DIM + n0 + bn;

    const int wid  = tid >> 5;
    const int lane = tid & 31;
    const int wm = wid >> 1;
    const int wn = wid & 1;
    const int g  = lane >> 2;
    const int tg = lane & 3;

    float acc[2][4][4] = {};

    const float4 z4 = make_float4(0.f, 0.f, 0.f, 0.f);
    float4 pa[4], pb[4];
    #pragma unroll
    for (int j = 0; j < 4; j++) {
        pa[j] = avalid ? *(const float4*)(aptr + j * 4) : z4;
        pb[j] = *(const float4*)(bptr + j * 4);
    }

    for (int k0 = 0; k0 < I_DIM; k0 += 32) {
        cvt8_hilo(pa[0], pa[1], &Ah[ar][akb],     &Al[ar][akb]);
        cvt8_hilo(pa[2], pa[3], &Ah[ar][akb + 8], &Al[ar][akb + 8]);
        cvt8_hi(pb[0], pb[1], &Bh[bk][bn]);
        cvt8_hi(pb[2], pb[3], &Bh[bk][bn + 8]);
        __syncthreads();

        if (k0 + 32 < I_DIM) {
            int kn = k0 + 32;
            const float* bp = bptr + (size_t)kn * H_DIM;
            #pragma unroll
            for (int j = 0; j < 4; j++) {
                pa[j] = avalid ? *(const float4*)(aptr + kn + j * 4) : z4;
                pb[j] = *(const float4*)(bp + j * 4);
            }
        }

        #pragma unroll
        for (int ks = 0; ks < 32; ks += 16) {
            uint32_t ah_f[2][4], al_f[2][4];
            #pragma unroll
            for (int mi = 0; mi < 2; mi++) {
                int row = wm * 32 + mi * 16 + (lane & 15);
                int col = ks + ((lane & 16) >> 1);
                ldsm4(ah_f[mi], smem_u32(&Ah[row][col]));
                ldsm4(al_f[mi], smem_u32(&Al[row][col]));
            }
            uint32_t b_f[4][2];
            #pragma unroll
            for (int ni = 0; ni < 4; ni++) {
                int brow = ks + (lane & 15);
                int bcol = wn * 32 + ni * 8;
                ldsm2t(b_f[ni], smem_u32(&Bh[brow][bcol]));
            }
            #pragma unroll
            for (int mi = 0; mi < 2; mi++) {
                #pragma unroll
                for (int ni = 0; ni < 4; ni++) {
                    mma16816(acc[mi][ni], ah_f[mi], b_f[ni]);
                    mma16816(acc[mi][ni], al_f[mi], b_f[ni]);
                }
            }
        }
        __syncthreads();
    }

    #pragma unroll
    for (int mi = 0; mi < 2; mi++) {
        int rr[2] = {m0 + wm * 32 + mi * 16 + g, m0 + wm * 32 + mi * 16 + g + 8};
        #pragma unroll
        for (int half = 0; half < 2; half++) {
            int r = rr[half];
            if (r >= nrows) continue;
            #pragma unroll
            for (int ni = 0; ni < 4; ni++) {
                int c0 = n0 + wn * 32 + ni * 8 + tg * 2;
                float v0 = acc[mi][ni][half * 2 + 0];
                float v1 = acc[mi][ni][half * 2 + 1];
                if (SHARED) {
                    float* orow = out + (size_t)r * H_DIM;
                    orow[c0]     = v0;
                    orow[c0 + 1] = v1;
                } else {
                    int slot = base + r;
                    int dest = g_dest[slot];
                    float w  = g_slotw[slot];
                    float* orow = g_partial + (size_t)dest * H_DIM;
                    orow[c0]     = w * v0;
                    orow[c0 + 1] = w * v1;
                }
            }
        }
    }
}

// ---------------- combine ----------------
__global__ void combine_kernel(float* __restrict__ out) {
    int i = blockIdx.x * blockDim.x + threadIdx.x;
    int t = i / H_DIM;
    int h = i - t * H_DIM;
    float acc = out[i];
    #pragma unroll
    for (int k = 0; k < TOPK; k++)
        acc += g_partial[((size_t)t * TOPK + k) * H_DIM + h];
    out[i] = acc;
}

// ---------------- launch ----------------
extern "C" void kernel_launch(void* const* d_in, const int* in_sizes, int n_in,
                              void* d_out, int out_size) {
    const float* x       = (const float*)d_in[0];
    const float* gate_w  = (const float*)d_in[1];
    const float* gate_b  = (const float*)d_in[2];
    const float* w_gate  = (const float*)d_in[3];
    const float* w_up    = (const float*)d_in[4];
    const float* w_down  = (const float*)d_in[5];
    const float* sw_gate = (const float*)d_in[6];
    const float* sw_up   = (const float*)d_in[7];
    const float* sw_down = (const float*)d_in[8];
    float* out = (float*)d_out;

    zero_counts_kernel<<<1, 64>>>();
    router_kernel<<<T_TOK, 64>>>(x, gate_w, gate_b);
    offsets_kernel<<<1, 1>>>();
    scatter_kernel<<<(T_TOK * TOPK + 255) / 256, 256>>>();

    gateup_kernel<false><<<dim3(I_DIM / 64, 8, E_NUM), 128>>>(x, w_gate, w_up);
    gateup_kernel<true><<<dim3(I_DIM / 64, T_TOK / 64, 1), 128>>>(x, sw_gate, sw_up);
    down_kernel<false><<<dim3(H_DIM / 64, 8, E_NUM), 128>>>(w_down, nullptr);
    down_kernel<true><<<dim3(H_DIM / 64, T_TOK / 64, 1), 128>>>(sw_down, out);
    combine_kernel<<<(T_TOK * H_DIM) / 256, 256>>>(out);
}